// round 1
// baseline (speedup 1.0000x reference)
#include <cuda_runtime.h>
#include <math_constants.h>
#include <math.h>

#define B_N   8192
#define D_X   384
#define H_N   256
#define C_N   6
#define KMAX  16
#define JSPLIT 4
#define JCHUNK (B_N / JSPLIT)

// -------- device scratch (no allocations allowed) --------
__device__ float g_sq[B_N];
__device__ int   g_k[B_N];
__device__ float g_h[(size_t)B_N * H_N];     // 8 MB
__device__ float g_agg[(size_t)B_N * H_N];   // 8 MB
__device__ float g_cd[(size_t)JSPLIT * B_N * KMAX];
__device__ int   g_ci[(size_t)JSPLIT * B_N * KMAX];
__device__ int   g_idx[(size_t)B_N * KMAX];

// ============================================================
// 1) per-row: sq = sum x^2 ; k = clip(round(16 - 12*sigmoid(x.Wtau+b)),1,16)
// ============================================================
__global__ void prep_kernel(const float* __restrict__ x,
                            const float* __restrict__ W_tau,
                            const float* __restrict__ b_tau) {
    int row = blockIdx.x;
    const float* xr = x + (size_t)row * D_X;
    float s = 0.f, tt = 0.f;
    for (int i = threadIdx.x; i < D_X; i += 128) {
        float v = xr[i];
        s  = fmaf(v, v, s);
        tt = fmaf(v, W_tau[i], tt);
    }
    #pragma unroll
    for (int o = 16; o > 0; o >>= 1) {
        s  += __shfl_xor_sync(~0u, s, o);
        tt += __shfl_xor_sync(~0u, tt, o);
    }
    __shared__ float sh[8];
    int w = threadIdx.x >> 5, l = threadIdx.x & 31;
    if (l == 0) { sh[w] = s; sh[4 + w] = tt; }
    __syncthreads();
    if (threadIdx.x == 0) {
        float S = sh[0] + sh[1] + sh[2] + sh[3];
        float T = sh[4] + sh[5] + sh[6] + sh[7] + b_tau[0];
        g_sq[row] = S;
        float tau = 1.f / (1.f + expf(-T));
        float kf  = rintf(16.f - 12.f * tau);        // round half-to-even, like jnp.round
        kf = fminf(fmaxf(kf, 1.f), 16.f);
        g_k[row] = (int)kf;
    }
}

// ============================================================
// 2) h = relu(x @ W_proj + b_proj)   [8192,256]
//    block = 64 rows, 256 threads (thread = output column)
// ============================================================
__global__ __launch_bounds__(256) void proj_kernel(const float* __restrict__ x,
                                                   const float* __restrict__ W_proj,
                                                   const float* __restrict__ b_proj) {
    __shared__ float sxt[16][65];
    int j = threadIdx.x;
    int rBlock = blockIdx.x * 64;
    float bp = b_proj[j];
    for (int c = 0; c < 4; c++) {
        int r0 = rBlock + c * 16;
        float acc[16];
        #pragma unroll
        for (int r = 0; r < 16; r++) acc[r] = 0.f;
        for (int kt = 0; kt < 6; kt++) {
            __syncthreads();
            #pragma unroll
            for (int l = 0; l < 4; l++) {
                int idx = threadIdx.x + l * 256;
                int rr = idx >> 6, kk = idx & 63;
                sxt[rr][kk] = x[(size_t)(r0 + rr) * D_X + kt * 64 + kk];
            }
            __syncthreads();
            for (int t = 0; t < 64; t++) {
                float w = W_proj[(size_t)(kt * 64 + t) * H_N + j];
                #pragma unroll
                for (int r = 0; r < 16; r++) acc[r] = fmaf(sxt[r][t], w, acc[r]);
            }
        }
        #pragma unroll
        for (int r = 0; r < 16; r++)
            g_h[(size_t)(r0 + r) * H_N + j] = fmaxf(acc[r] + bp, 0.f);
    }
}

// ============================================================
// 3) fused pairwise-distance + per-row top-16 (partial, per j-split)
//    grid (64, 4): 128-row tile x 2048-column range per block, 256 threads
// ============================================================
#define KNN_SMEM ((16*129*2 + 128*129 + 256) * 4)

__global__ __launch_bounds__(256) void knn_kernel(const float* __restrict__ x) {
    extern __shared__ float sm[];
    float* sX  = sm;                 // [16][129]
    float* sY  = sX + 16 * 129;      // [16][129]
    float* sD  = sY + 16 * 129;      // [128][129]
    float* sqi = sD + 128 * 129;     // [128]
    float* sqj = sqi + 128;          // [128]

    int tid = threadIdx.x, tx = tid & 15, ty = tid >> 4;
    int rowBase  = blockIdx.x * 128;
    int colStart = blockIdx.y * JCHUNK;
    if (tid < 128) sqi[tid] = g_sq[rowBase + tid];

    float dist[16]; int idxr[16];
    #pragma unroll
    for (int p = 0; p < 16; p++) { dist[p] = CUDART_INF_F; idxr[p] = 0x7fffffff; }

    for (int jt = 0; jt < JCHUNK / 128; jt++) {
        int colBase = colStart + jt * 128;
        if (tid < 128) sqj[tid] = g_sq[colBase + tid];

        float acc[8][8];
        #pragma unroll
        for (int i = 0; i < 8; i++)
            #pragma unroll
            for (int jm = 0; jm < 8; jm++) acc[i][jm] = 0.f;

        for (int kc = 0; kc < D_X; kc += 16) {
            __syncthreads();  // also protects sqj write & previous-tile scan
            int k = tid & 15, mB = tid >> 4;
            #pragma unroll
            for (int i = 0; i < 8; i++) {
                int m = mB + i * 16;
                sX[k * 129 + m] = x[(size_t)(rowBase + m) * D_X + kc + k];
                sY[k * 129 + m] = x[(size_t)(colBase + m) * D_X + kc + k];
            }
            __syncthreads();
            #pragma unroll
            for (int kk = 0; kk < 16; kk++) {
                float a[8], b[8];
                #pragma unroll
                for (int i = 0; i < 8; i++)  a[i]  = sX[kk * 129 + ty + i * 16];
                #pragma unroll
                for (int jm = 0; jm < 8; jm++) b[jm] = sY[kk * 129 + tx + jm * 16];
                #pragma unroll
                for (int i = 0; i < 8; i++)
                    #pragma unroll
                    for (int jm = 0; jm < 8; jm++)
                        acc[i][jm] = fmaf(a[i], b[jm], acc[i][jm]);
            }
        }
        // d2 tile -> smem (row stride 129: conflict-free column scan)
        #pragma unroll
        for (int i = 0; i < 8; i++) {
            int r = ty + i * 16;
            #pragma unroll
            for (int jm = 0; jm < 8; jm++) {
                int c = tx + jm * 16;
                sD[r * 129 + c] = sqi[r] + sqj[c] - 2.f * acc[i][jm];
            }
        }
        __syncthreads();
        // owner scan: thread t owns row t, sorted-insert into register top-16
        if (tid < 128) {
            for (int c = 0; c < 128; c++) {
                float d = sD[tid * 129 + c];
                if (d < dist[15]) {           // strict: earlier j wins ties (ascending scan)
                    float dd = d; int jj = colBase + c;
                    #pragma unroll
                    for (int p = 0; p < 16; p++) {
                        if (dd < dist[p]) {
                            float td = dist[p]; dist[p] = dd; dd = td;
                            int   tj = idxr[p]; idxr[p] = jj; jj = tj;
                        }
                    }
                }
            }
        }
    }
    if (tid < 128) {
        int row = rowBase + tid;
        size_t base = ((size_t)blockIdx.y * B_N + row) * KMAX;
        #pragma unroll
        for (int p = 0; p < 16; p++) { g_cd[base + p] = dist[p]; g_ci[base + p] = idxr[p]; }
    }
}

// ============================================================
// 4) merge the 4 partial top-16 lists -> exact global top-16
//    lexicographic (dist, idx) comparator == jax.lax.top_k tie-breaking
// ============================================================
__global__ void merge_kernel() {
    int row = blockIdx.x * 256 + threadIdx.x;
    float dist[16]; int idxr[16];
    #pragma unroll
    for (int p = 0; p < 16; p++) { dist[p] = CUDART_INF_F; idxr[p] = 0x7fffffff; }
    for (int s = 0; s < JSPLIT; s++) {
        size_t base = ((size_t)s * B_N + row) * KMAX;
        for (int q = 0; q < 16; q++) {
            float d = g_cd[base + q]; int j = g_ci[base + q];
            bool enter = (d < dist[15]) || (d == dist[15] && j < idxr[15]);
            if (enter) {
                float dd = d; int jj = j;
                #pragma unroll
                for (int p = 0; p < 16; p++) {
                    bool lt = (dd < dist[p]) || (dd == dist[p] && jj < idxr[p]);
                    if (lt) {
                        float td = dist[p]; dist[p] = dd; dd = td;
                        int   tj = idxr[p]; idxr[p] = jj; jj = tj;
                    }
                }
            }
        }
    }
    #pragma unroll
    for (int p = 0; p < 16; p++) g_idx[(size_t)row * KMAX + p] = idxr[p];
}

// ============================================================
// 5) agg = mean of first k gathered h rows
// ============================================================
__global__ void agg_kernel() {
    int row = blockIdx.x, j = threadIdx.x;
    __shared__ int sidx[16];
    __shared__ int sk;
    if (j < 16) sidx[j] = g_idx[(size_t)row * KMAX + j];
    if (j == 0) sk = g_k[row];
    __syncthreads();
    int k = sk;
    float s = 0.f;
    for (int t = 0; t < k; t++) s += g_h[(size_t)sidx[t] * H_N + j];
    g_agg[(size_t)row * H_N + j] = s / (float)k;
}

// ============================================================
// 6) r = relu(agg@W_res + b_res); z = h + r; LayerNorm; out = (zn*g+b)@W_fc + b_fc
//    block = 16 rows, 256 threads (thread = column for GEMM phase)
// ============================================================
__global__ __launch_bounds__(256) void resln_kernel(const float* __restrict__ W_res,
                                                    const float* __restrict__ b_res,
                                                    const float* __restrict__ ln_g,
                                                    const float* __restrict__ ln_b,
                                                    const float* __restrict__ W_fc,
                                                    const float* __restrict__ b_fc,
                                                    float* __restrict__ out) {
    __shared__ float sAgg[16][256];
    __shared__ float sZ[16][256];
    __shared__ float sG[256], sBn[256], sWfc[256 * 6], sbfc[6];
    int j = threadIdx.x;
    int r0 = blockIdx.x * 16;
    #pragma unroll
    for (int r = 0; r < 16; r++) sAgg[r][j] = g_agg[(size_t)(r0 + r) * H_N + j];
    sG[j] = ln_g[j]; sBn[j] = ln_b[j];
    for (int l = j; l < 256 * 6; l += 256) sWfc[l] = W_fc[l];
    if (j < 6) sbfc[j] = b_fc[j];
    float br = b_res[j];
    __syncthreads();

    float acc[16];
    #pragma unroll
    for (int r = 0; r < 16; r++) acc[r] = 0.f;
    for (int t = 0; t < 256; t++) {
        float w = W_res[(size_t)t * H_N + j];
        #pragma unroll
        for (int r = 0; r < 16; r++) acc[r] = fmaf(sAgg[r][t], w, acc[r]);
    }
    #pragma unroll
    for (int r = 0; r < 16; r++) {
        float rv = fmaxf(acc[r] + br, 0.f);
        sZ[r][j] = g_h[(size_t)(r0 + r) * H_N + j] + rv;
    }
    __syncthreads();

    int wid = j >> 5, lane = j & 31;
    for (int rr = 0; rr < 2; rr++) {
        int lr = wid * 2 + rr;
        int row = r0 + lr;
        float zv[8]; float s = 0.f, s2 = 0.f;
        #pragma unroll
        for (int q = 0; q < 8; q++) {
            zv[q] = sZ[lr][lane + q * 32];
            s += zv[q]; s2 = fmaf(zv[q], zv[q], s2);
        }
        #pragma unroll
        for (int o = 16; o > 0; o >>= 1) {
            s  += __shfl_xor_sync(~0u, s,  o);
            s2 += __shfl_xor_sync(~0u, s2, o);
        }
        float mu   = s * (1.f / 256.f);
        float var  = s2 * (1.f / 256.f) - mu * mu;
        float rstd = 1.0f / sqrtf(var + 1e-5f);
        float po[6] = {0, 0, 0, 0, 0, 0};
        #pragma unroll
        for (int q = 0; q < 8; q++) {
            int t = lane + q * 32;
            float a = (zv[q] - mu) * rstd * sG[t] + sBn[t];
            #pragma unroll
            for (int c = 0; c < 6; c++) po[c] = fmaf(a, sWfc[t * 6 + c], po[c]);
        }
        #pragma unroll
        for (int c = 0; c < 6; c++) {
            #pragma unroll
            for (int o = 16; o > 0; o >>= 1) po[c] += __shfl_xor_sync(~0u, po[c], o);
        }
        if (lane == 0) {
            #pragma unroll
            for (int c = 0; c < 6; c++) out[(size_t)row * C_N + c] = po[c] + sbfc[c];
        }
    }
}

// ============================================================
extern "C" void kernel_launch(void* const* d_in, const int* in_sizes, int n_in,
                              void* d_out, int out_size) {
    const float* x      = (const float*)d_in[0];
    const float* W_proj = (const float*)d_in[1];
    const float* b_proj = (const float*)d_in[2];
    const float* W_tau  = (const float*)d_in[3];
    const float* b_tau  = (const float*)d_in[4];
    const float* W_res  = (const float*)d_in[5];
    const float* b_res  = (const float*)d_in[6];
    const float* ln_g   = (const float*)d_in[7];
    const float* ln_b   = (const float*)d_in[8];
    const float* W_fc   = (const float*)d_in[9];
    const float* b_fc   = (const float*)d_in[10];
    float* out = (float*)d_out;

    cudaFuncSetAttribute(knn_kernel, cudaFuncAttributeMaxDynamicSharedMemorySize, KNN_SMEM);

    prep_kernel<<<B_N, 128>>>(x, W_tau, b_tau);
    proj_kernel<<<B_N / 64, 256>>>(x, W_proj, b_proj);
    dim3 g(B_N / 128, JSPLIT);
    knn_kernel<<<g, 256, KNN_SMEM>>>(x);
    merge_kernel<<<B_N / 256, 256>>>();
    agg_kernel<<<B_N, 256>>>();
    resln_kernel<<<B_N / 16, 256>>>(W_res, b_res, ln_g, ln_b, W_fc, b_fc, out);
}

// round 3
// speedup vs baseline: 2.4365x; 2.4365x over previous
#include <cuda_runtime.h>
#include <cuda_bf16.h>
#include <math_constants.h>
#include <math.h>
#include <stdint.h>

#define B_N   8192
#define D_X   384
#define H_N   256
#define C_N   6
#define KMAX  16
#define JSPLIT 4
#define JCHUNK (B_N / JSPLIT)      // 2048
#define MTILE 128
#define NTILE 128
#define NT_PER (JCHUNK / NTILE)    // 16
#define KPACK (3 * D_X)            // 1152
#define KSTEP 64                   // bf16 per stage (128 B/row)
#define NKSTAGE (KPACK / KSTEP)    // 18
#define STAGE_B 32768              // A 16K + B 16K
#define KNN_SMEM (1024 + 3 * STAGE_B)  // 99328

// -------- device scratch --------
__device__ float g_sq[B_N];
__device__ int   g_k[B_N];
__device__ __align__(16) __nv_bfloat16 g_xa[(size_t)B_N * KPACK];  // [hi|hi|lo]
__device__ __align__(16) __nv_bfloat16 g_xb[(size_t)B_N * KPACK];  // [hi|lo|hi]
__device__ float g_h[(size_t)B_N * H_N];
__device__ float g_agg[(size_t)B_N * H_N];
__device__ float g_cd[(size_t)JSPLIT * B_N * KMAX];
__device__ int   g_ci[(size_t)JSPLIT * B_N * KMAX];
__device__ int   g_idx[(size_t)B_N * KMAX];

// ================= PTX helpers (portable, no tcgen05) =================
__device__ __forceinline__ uint32_t smem_u32(const void* p) {
    uint32_t a;
    asm("{ .reg .u64 t; cvta.to.shared.u64 t, %1; cvt.u32.u64 %0, t; }" : "=r"(a) : "l"(p));
    return a;
}
#define CP_ASYNC16(s, g) asm volatile("cp.async.cg.shared.global [%0], [%1], 16;" :: "r"(s), "l"(g))
#define CP_COMMIT()      asm volatile("cp.async.commit_group;")
#define CP_WAIT1()       asm volatile("cp.async.wait_group 1;")
#define CP_WAIT0()       asm volatile("cp.async.wait_group 0;")

#define LDSM4(r0, r1, r2, r3, addr) \
    asm volatile("ldmatrix.sync.aligned.m8n8.x4.shared.b16 {%0,%1,%2,%3}, [%4];" \
        : "=r"(r0), "=r"(r1), "=r"(r2), "=r"(r3) : "r"(addr))

#define MMA16816(c, a, b0, b1) \
    asm volatile("mma.sync.aligned.m16n8k16.row.col.f32.bf16.bf16.f32 " \
        "{%0,%1,%2,%3}, {%4,%5,%6,%7}, {%8,%9}, {%0,%1,%2,%3};" \
        : "+f"((c)[0]), "+f"((c)[1]), "+f"((c)[2]), "+f"((c)[3]) \
        : "r"((a)[0]), "r"((a)[1]), "r"((a)[2]), "r"((a)[3]), "r"(b0), "r"(b1))

// ============================================================
// 0) pack x into bf16 split arrays: A'=[hi|hi|lo], B'=[hi|lo|hi]
// ============================================================
__global__ void pack_kernel(const float* __restrict__ x) {
    int i = blockIdx.x * 256 + threadIdx.x;      // float4 group; 786432 total
    float4 v = ((const float4*)x)[i];
    int row = i / (D_X / 4);
    int c4  = (i % (D_X / 4)) * 4;
    float f[4] = {v.x, v.y, v.z, v.w};
    __nv_bfloat16 h[4], l[4];
    #pragma unroll
    for (int q = 0; q < 4; q++) {
        h[q] = __float2bfloat16(f[q]);
        l[q] = __float2bfloat16(f[q] - __bfloat162float(h[q]));
    }
    __nv_bfloat162 h0; h0.x = h[0]; h0.y = h[1];
    __nv_bfloat162 h1; h1.x = h[2]; h1.y = h[3];
    __nv_bfloat162 l0; l0.x = l[0]; l0.y = l[1];
    __nv_bfloat162 l1; l1.x = l[2]; l1.y = l[3];
    __nv_bfloat16* A = g_xa + (size_t)row * KPACK + c4;
    __nv_bfloat16* Bp = g_xb + (size_t)row * KPACK + c4;
    *(__nv_bfloat162*)(A)           = h0; *(__nv_bfloat162*)(A + 2)           = h1;
    *(__nv_bfloat162*)(A + 384)     = h0; *(__nv_bfloat162*)(A + 386)         = h1;
    *(__nv_bfloat162*)(A + 768)     = l0; *(__nv_bfloat162*)(A + 770)         = l1;
    *(__nv_bfloat162*)(Bp)          = h0; *(__nv_bfloat162*)(Bp + 2)          = h1;
    *(__nv_bfloat162*)(Bp + 384)    = l0; *(__nv_bfloat162*)(Bp + 386)        = l1;
    *(__nv_bfloat162*)(Bp + 768)    = h0; *(__nv_bfloat162*)(Bp + 770)        = h1;
}

// ============================================================
// 1) per-row: sq = sum x^2 ; adaptive k
// ============================================================
__global__ void prep_kernel(const float* __restrict__ x,
                            const float* __restrict__ W_tau,
                            const float* __restrict__ b_tau) {
    int row = blockIdx.x;
    const float* xr = x + (size_t)row * D_X;
    float s = 0.f, tt = 0.f;
    for (int i = threadIdx.x; i < D_X; i += 128) {
        float v = xr[i];
        s  = fmaf(v, v, s);
        tt = fmaf(v, W_tau[i], tt);
    }
    #pragma unroll
    for (int o = 16; o > 0; o >>= 1) {
        s  += __shfl_xor_sync(~0u, s, o);
        tt += __shfl_xor_sync(~0u, tt, o);
    }
    __shared__ float sh[8];
    int w = threadIdx.x >> 5, l = threadIdx.x & 31;
    if (l == 0) { sh[w] = s; sh[4 + w] = tt; }
    __syncthreads();
    if (threadIdx.x == 0) {
        float S = sh[0] + sh[1] + sh[2] + sh[3];
        float T = sh[4] + sh[5] + sh[6] + sh[7] + b_tau[0];
        g_sq[row] = S;
        float tau = 1.f / (1.f + expf(-T));
        float kf  = rintf(16.f - 12.f * tau);
        kf = fminf(fmaxf(kf, 1.f), 16.f);
        g_k[row] = (int)kf;
    }
}

// ============================================================
// 2) h = relu(x @ W_proj + b_proj)
// ============================================================
__global__ __launch_bounds__(256) void proj_kernel(const float* __restrict__ x,
                                                   const float* __restrict__ W_proj,
                                                   const float* __restrict__ b_proj) {
    __shared__ float sxt[16][65];
    int j = threadIdx.x;
    int rBlock = blockIdx.x * 64;
    float bp = b_proj[j];
    for (int c = 0; c < 4; c++) {
        int r0 = rBlock + c * 16;
        float acc[16];
        #pragma unroll
        for (int r = 0; r < 16; r++) acc[r] = 0.f;
        for (int kt = 0; kt < 6; kt++) {
            __syncthreads();
            #pragma unroll
            for (int l = 0; l < 4; l++) {
                int idx = threadIdx.x + l * 256;
                int rr = idx >> 6, kk = idx & 63;
                sxt[rr][kk] = x[(size_t)(r0 + rr) * D_X + kt * 64 + kk];
            }
            __syncthreads();
            for (int t = 0; t < 64; t++) {
                float w = W_proj[(size_t)(kt * 64 + t) * H_N + j];
                #pragma unroll
                for (int r = 0; r < 16; r++) acc[r] = fmaf(sxt[r][t], w, acc[r]);
            }
        }
        #pragma unroll
        for (int r = 0; r < 16; r++)
            g_h[(size_t)(r0 + r) * H_N + j] = fmaxf(acc[r] + bp, 0.f);
    }
}

// ============================================================
// 3) bf16 mma.sync pairwise dot + fused top-16
//    grid (64, 4): 128 rows x 2048 cols per CTA; 256 threads, 8 warps (2x4)
// ============================================================
__device__ __forceinline__ void stage_load(uint32_t sbase,
                                           const __nv_bfloat16* gA,
                                           const __nv_bfloat16* gB, int tid) {
    #pragma unroll
    for (int it = 0; it < 4; it++) {
        int idx = tid + it * 256;          // 0..1023
        int r = idx >> 3, c = idx & 7;
        uint32_t off = (uint32_t)(r * 128 + c * 16);
        off ^= (off >> 3) & 0x70;
        CP_ASYNC16(sbase + off,         (const char*)(gA + (size_t)r * KPACK) + c * 16);
        CP_ASYNC16(sbase + 16384 + off, (const char*)(gB + (size_t)r * KPACK) + c * 16);
    }
}

__global__ __launch_bounds__(256, 2) void knn_kernel() {
    extern __shared__ char smem[];
    uint32_t smem_base = smem_u32(smem);
    float* sqj = (float*)smem;
    int tid = threadIdx.x, lane = tid & 31, warp = tid >> 5;
    int wm = warp >> 2, wn = warp & 3;

    int rowBase  = blockIdx.x * MTILE;
    int colStart = blockIdx.y * JCHUNK;

    // ldmatrix lane-address invariants
    int a_hi = (lane >> 4) & 1;                                   // A k-chunk select
    int b_hi = (lane >> 3) & 1;                                   // B k-chunk select
    int aRow = wm * 64 + (lane & 15);
    int bRow = wn * 32 + (lane & 7) + (((lane >> 4) & 1) << 3);
    uint32_t arow_off[4], arow_x[4], brow_off[2], brow_x[2];
    #pragma unroll
    for (int i = 0; i < 4; i++) { int r = aRow + i * 16; arow_off[i] = r * 128; arow_x[i] = r & 7; }
    #pragma unroll
    for (int p = 0; p < 2; p++) { int r = bRow + p * 16; brow_off[p] = r * 128; brow_x[p] = r & 7; }

    float dist[16]; int idxr[16];
    #pragma unroll
    for (int p = 0; p < 16; p++) { dist[p] = CUDART_INF_F; idxr[p] = 0x7fffffff; }

    const __nv_bfloat16* gA0 = g_xa + (size_t)rowBase * KPACK;

    for (int t = 0; t < NT_PER; t++) {
        int colBase = colStart + t * NTILE;
        __syncthreads();                     // protect prev sD/sqj reads
        if (tid < 128) sqj[tid] = g_sq[colBase + tid];
        const __nv_bfloat16* gB0 = g_xb + (size_t)colBase * KPACK;

        stage_load(smem_base + 1024,           gA0,         gB0,         tid); CP_COMMIT();
        stage_load(smem_base + 1024 + STAGE_B, gA0 + KSTEP, gB0 + KSTEP, tid); CP_COMMIT();

        float acc[4][4][4];
        #pragma unroll
        for (int i = 0; i < 4; i++)
            #pragma unroll
            for (int j = 0; j < 4; j++)
                #pragma unroll
                for (int q = 0; q < 4; q++) acc[i][j][q] = 0.f;

        for (int s = 0; s < NKSTAGE; s++) {
            if (s + 2 < NKSTAGE) { CP_WAIT1(); } else { CP_WAIT0(); }
            __syncthreads();
            if (s + 2 < NKSTAGE) {
                stage_load(smem_base + 1024 + ((s + 2) % 3) * STAGE_B,
                           gA0 + (s + 2) * KSTEP, gB0 + (s + 2) * KSTEP, tid);
                CP_COMMIT();
            }
            uint32_t stA = smem_base + 1024 + (s % 3) * STAGE_B;
            uint32_t stB = stA + 16384;
            #pragma unroll
            for (int kk = 0; kk < 4; kk++) {
                uint32_t a[4][4], b[2][4];
                #pragma unroll
                for (int i = 0; i < 4; i++) {
                    uint32_t ck = (uint32_t)(2 * kk + a_hi);
                    uint32_t ad = stA + arow_off[i] + ((ck ^ arow_x[i]) << 4);
                    LDSM4(a[i][0], a[i][1], a[i][2], a[i][3], ad);
                }
                #pragma unroll
                for (int p = 0; p < 2; p++) {
                    uint32_t ck = (uint32_t)(2 * kk + b_hi);
                    uint32_t ad = stB + brow_off[p] + ((ck ^ brow_x[p]) << 4);
                    LDSM4(b[p][0], b[p][1], b[p][2], b[p][3], ad);
                }
                #pragma unroll
                for (int i = 0; i < 4; i++)
                    #pragma unroll
                    for (int j = 0; j < 4; j++)
                        MMA16816(acc[i][j], a[i], b[j >> 1][(j & 1) * 2], b[j >> 1][(j & 1) * 2 + 1]);
            }
        }

        // ---- epilogue: acc -> smem d-tile -> owner top-16 scan ----
        __syncthreads();
        float* sD = (float*)(smem + 1024);
        int r0l = wm * 64 + (lane >> 2);
        int c0l = wn * 32 + (lane & 3) * 2;
        #pragma unroll
        for (int i = 0; i < 4; i++) {
            int r = r0l + i * 16;
            #pragma unroll
            for (int j = 0; j < 4; j++) {
                int c = c0l + j * 8;
                sD[r * 129 + c]           = acc[i][j][0];
                sD[r * 129 + c + 1]       = acc[i][j][1];
                sD[(r + 8) * 129 + c]     = acc[i][j][2];
                sD[(r + 8) * 129 + c + 1] = acc[i][j][3];
            }
        }
        __syncthreads();
        if (tid < 128) {
            #pragma unroll 4
            for (int c = 0; c < 128; c++) {
                float d = fmaf(-2.f, sD[tid * 129 + c], sqj[c]);
                if (d < dist[15]) {
                    float dd = d; int jj = colBase + c;
                    #pragma unroll
                    for (int p = 0; p < 16; p++) {
                        if (dd < dist[p]) {
                            float td = dist[p]; dist[p] = dd; dd = td;
                            int   tj = idxr[p]; idxr[p] = jj; jj = tj;
                        }
                    }
                }
            }
        }
    }

    if (tid < 128) {
        int row = rowBase + tid;
        size_t base = ((size_t)blockIdx.y * B_N + row) * KMAX;
        #pragma unroll
        for (int p = 0; p < 16; p++) { g_cd[base + p] = dist[p]; g_ci[base + p] = idxr[p]; }
    }
}

// ============================================================
// 4) merge 4 partial top-16 lists (lexicographic (dist, idx))
// ============================================================
__global__ void merge_kernel() {
    int row = blockIdx.x * 64 + threadIdx.x;
    float dist[16]; int idxr[16];
    #pragma unroll
    for (int p = 0; p < 16; p++) { dist[p] = CUDART_INF_F; idxr[p] = 0x7fffffff; }
    for (int s = 0; s < JSPLIT; s++) {
        size_t base = ((size_t)s * B_N + row) * KMAX;
        for (int q = 0; q < 16; q++) {
            float d = g_cd[base + q]; int j = g_ci[base + q];
            bool enter = (d < dist[15]) || (d == dist[15] && j < idxr[15]);
            if (enter) {
                float dd = d; int jj = j;
                #pragma unroll
                for (int p = 0; p < 16; p++) {
                    bool lt = (dd < dist[p]) || (dd == dist[p] && jj < idxr[p]);
                    if (lt) {
                        float td = dist[p]; dist[p] = dd; dd = td;
                        int   tj = idxr[p]; idxr[p] = jj; jj = tj;
                    }
                }
            }
        }
    }
    #pragma unroll
    for (int p = 0; p < 16; p++) g_idx[(size_t)row * KMAX + p] = idxr[p];
}

// ============================================================
// 5) agg = mean of first k gathered h rows
// ============================================================
__global__ void agg_kernel() {
    int row = blockIdx.x, j = threadIdx.x;
    __shared__ int sidx[16];
    __shared__ int sk;
    if (j < 16) sidx[j] = g_idx[(size_t)row * KMAX + j];
    if (j == 0) sk = g_k[row];
    __syncthreads();
    int k = sk;
    float s = 0.f;
    for (int t = 0; t < k; t++) s += g_h[(size_t)sidx[t] * H_N + j];
    g_agg[(size_t)row * H_N + j] = s / (float)k;
}

// ============================================================
// 6) residual + LayerNorm + fc
// ============================================================
__global__ __launch_bounds__(256) void resln_kernel(const float* __restrict__ W_res,
                                                    const float* __restrict__ b_res,
                                                    const float* __restrict__ ln_g,
                                                    const float* __restrict__ ln_b,
                                                    const float* __restrict__ W_fc,
                                                    const float* __restrict__ b_fc,
                                                    float* __restrict__ out) {
    __shared__ float sAgg[16][256];
    __shared__ float sZ[16][256];
    __shared__ float sG[256], sBn[256], sWfc[256 * 6], sbfc[6];
    int j = threadIdx.x;
    int r0 = blockIdx.x * 16;
    #pragma unroll
    for (int r = 0; r < 16; r++) sAgg[r][j] = g_agg[(size_t)(r0 + r) * H_N + j];
    sG[j] = ln_g[j]; sBn[j] = ln_b[j];
    for (int l = j; l < 256 * 6; l += 256) sWfc[l] = W_fc[l];
    if (j < 6) sbfc[j] = b_fc[j];
    float br = b_res[j];
    __syncthreads();

    float acc[16];
    #pragma unroll
    for (int r = 0; r < 16; r++) acc[r] = 0.f;
    for (int t = 0; t < 256; t++) {
        float w = W_res[(size_t)t * H_N + j];
        #pragma unroll
        for (int r = 0; r < 16; r++) acc[r] = fmaf(sAgg[r][t], w, acc[r]);
    }
    #pragma unroll
    for (int r = 0; r < 16; r++) {
        float rv = fmaxf(acc[r] + br, 0.f);
        sZ[r][j] = g_h[(size_t)(r0 + r) * H_N + j] + rv;
    }
    __syncthreads();

    int wid = j >> 5, lane = j & 31;
    for (int rr = 0; rr < 2; rr++) {
        int lr = wid * 2 + rr;
        int row = r0 + lr;
        float zv[8]; float s = 0.f, s2 = 0.f;
        #pragma unroll
        for (int q = 0; q < 8; q++) {
            zv[q] = sZ[lr][lane + q * 32];
            s += zv[q]; s2 = fmaf(zv[q], zv[q], s2);
        }
        #pragma unroll
        for (int o = 16; o > 0; o >>= 1) {
            s  += __shfl_xor_sync(~0u, s,  o);
            s2 += __shfl_xor_sync(~0u, s2, o);
        }
        float mu   = s * (1.f / 256.f);
        float var  = s2 * (1.f / 256.f) - mu * mu;
        float rstd = 1.0f / sqrtf(var + 1e-5f);
        float po[6] = {0, 0, 0, 0, 0, 0};
        #pragma unroll
        for (int q = 0; q < 8; q++) {
            int tcol = lane + q * 32;
            float a = (zv[q] - mu) * rstd * sG[tcol] + sBn[tcol];
            #pragma unroll
            for (int c = 0; c < 6; c++) po[c] = fmaf(a, sWfc[tcol * 6 + c], po[c]);
        }
        #pragma unroll
        for (int c = 0; c < 6; c++) {
            #pragma unroll
            for (int o = 16; o > 0; o >>= 1) po[c] += __shfl_xor_sync(~0u, po[c], o);
        }
        if (lane == 0) {
            #pragma unroll
            for (int c = 0; c < 6; c++) out[(size_t)row * C_N + c] = po[c] + sbfc[c];
        }
    }
}

// ============================================================
extern "C" void kernel_launch(void* const* d_in, const int* in_sizes, int n_in,
                              void* d_out, int out_size) {
    const float* x      = (const float*)d_in[0];
    const float* W_proj = (const float*)d_in[1];
    const float* b_proj = (const float*)d_in[2];
    const float* W_tau  = (const float*)d_in[3];
    const float* b_tau  = (const float*)d_in[4];
    const float* W_res  = (const float*)d_in[5];
    const float* b_res  = (const float*)d_in[6];
    const float* ln_g   = (const float*)d_in[7];
    const float* ln_b   = (const float*)d_in[8];
    const float* W_fc   = (const float*)d_in[9];
    const float* b_fc   = (const float*)d_in[10];
    float* out = (float*)d_out;

    cudaFuncSetAttribute(knn_kernel, cudaFuncAttributeMaxDynamicSharedMemorySize, KNN_SMEM);

    prep_kernel<<<B_N, 128>>>(x, W_tau, b_tau);
    pack_kernel<<<(B_N * D_X / 4) / 256, 256>>>(x);
    proj_kernel<<<B_N / 64, 256>>>(x, W_proj, b_proj);
    dim3 g(B_N / MTILE, JSPLIT);
    knn_kernel<<<g, 256, KNN_SMEM>>>();
    merge_kernel<<<B_N / 64, 64>>>();
    agg_kernel<<<B_N, 256>>>();
    resln_kernel<<<B_N / 16, 256>>>(W_res, b_res, ln_g, ln_b, W_fc, b_fc, out);
}

// round 4
// speedup vs baseline: 2.8710x; 1.1783x over previous
#include <cuda_runtime.h>
#include <cuda_bf16.h>
#include <math_constants.h>
#include <math.h>
#include <stdint.h>

#define B_N   8192
#define D_X   384
#define H_N   256
#define C_N   6
#define KMAX  16
#define JSPLIT 4
#define JCHUNK (B_N / JSPLIT)      // 2048
#define MTILE 128
#define NTILE 128
#define NT_PER (JCHUNK / NTILE)    // 16
#define KPACK (2 * D_X)            // 768 stored ([hi|lo])
#define KSTEP 64                   // bf16 per stage (128 B/row)
#define NKSTAGE 18                 // 3-term virtual K = 1152
#define STAGE_B 32768              // A 16K + B 16K
#define KNN_SMEM (1024 + 3 * STAGE_B)  // 99328

// -------- device scratch --------
__device__ float g_sq[B_N];
__device__ int   g_k[B_N];
__device__ __align__(16) __nv_bfloat16 g_xp[(size_t)B_N * KPACK];  // x packed [hi|lo]
__device__ __align__(16) __nv_bfloat16 g_wp[(size_t)H_N * KPACK];  // W_proj^T packed [hi|lo]
__device__ float g_h[(size_t)B_N * H_N];
__device__ float g_cd[(size_t)JSPLIT * B_N * KMAX];
__device__ int   g_ci[(size_t)JSPLIT * B_N * KMAX];
__device__ int   g_idx[(size_t)B_N * KMAX];

// virtual-K stage -> element offset in packed array
__device__ __forceinline__ int aOffE(int s) { return (s < 6 ? s : s - 6) * KSTEP; }   // [hi|hi|lo]
__device__ __forceinline__ int bOffE(int s) { return (s < 12 ? s : s - 12) * KSTEP; } // [hi|lo|hi]

// ================= PTX helpers (portable) =================
__device__ __forceinline__ uint32_t smem_u32(const void* p) {
    uint32_t a;
    asm("{ .reg .u64 t; cvta.to.shared.u64 t, %1; cvt.u32.u64 %0, t; }" : "=r"(a) : "l"(p));
    return a;
}
#define CP_ASYNC16(s, g) asm volatile("cp.async.cg.shared.global [%0], [%1], 16;" :: "r"(s), "l"(g))
#define CP_COMMIT()      asm volatile("cp.async.commit_group;")
#define CP_WAIT1()       asm volatile("cp.async.wait_group 1;")
#define CP_WAIT0()       asm volatile("cp.async.wait_group 0;")

#define LDSM4(r0, r1, r2, r3, addr) \
    asm volatile("ldmatrix.sync.aligned.m8n8.x4.shared.b16 {%0,%1,%2,%3}, [%4];" \
        : "=r"(r0), "=r"(r1), "=r"(r2), "=r"(r3) : "r"(addr))

#define MMA16816(c, a, b0, b1) \
    asm volatile("mma.sync.aligned.m16n8k16.row.col.f32.bf16.bf16.f32 " \
        "{%0,%1,%2,%3}, {%4,%5,%6,%7}, {%8,%9}, {%0,%1,%2,%3};" \
        : "+f"((c)[0]), "+f"((c)[1]), "+f"((c)[2]), "+f"((c)[3]) \
        : "r"((a)[0]), "r"((a)[1]), "r"((a)[2]), "r"((a)[3]), "r"(b0), "r"(b1))

// ============================================================
// 0a) pack x -> [hi|lo] bf16
// ============================================================
__global__ void pack_kernel(const float* __restrict__ x) {
    int i = blockIdx.x * 256 + threadIdx.x;      // float4 group; 786432 total
    float4 v = ((const float4*)x)[i];
    int row = i / (D_X / 4);
    int c4  = (i % (D_X / 4)) * 4;
    float f[4] = {v.x, v.y, v.z, v.w};
    __nv_bfloat16 h[4], l[4];
    #pragma unroll
    for (int q = 0; q < 4; q++) {
        h[q] = __float2bfloat16(f[q]);
        l[q] = __float2bfloat16(f[q] - __bfloat162float(h[q]));
    }
    __nv_bfloat16* P = g_xp + (size_t)row * KPACK + c4;
    __nv_bfloat162 h0; h0.x = h[0]; h0.y = h[1];
    __nv_bfloat162 h1; h1.x = h[2]; h1.y = h[3];
    __nv_bfloat162 l0; l0.x = l[0]; l0.y = l[1];
    __nv_bfloat162 l1; l1.x = l[2]; l1.y = l[3];
    *(__nv_bfloat162*)(P)         = h0; *(__nv_bfloat162*)(P + 2)         = h1;
    *(__nv_bfloat162*)(P + D_X)   = l0; *(__nv_bfloat162*)(P + D_X + 2)   = l1;
}

// 0b) pack W_proj^T -> [hi|lo] bf16  (W is [D_X][H_N] row-major)
__global__ void packw_kernel(const float* __restrict__ W) {
    int i = blockIdx.x * 256 + threadIdx.x;      // 0..98303
    int k = i / H_N, n = i % H_N;                // coalesced read
    float f = W[i];
    __nv_bfloat16 h = __float2bfloat16(f);
    __nv_bfloat16 l = __float2bfloat16(f - __bfloat162float(h));
    g_wp[(size_t)n * KPACK + k]       = h;
    g_wp[(size_t)n * KPACK + D_X + k] = l;
}

// ============================================================
// 1) per-row: sq = sum x^2 ; adaptive k
// ============================================================
__global__ void prep_kernel(const float* __restrict__ x,
                            const float* __restrict__ W_tau,
                            const float* __restrict__ b_tau) {
    int row = blockIdx.x;
    const float* xr = x + (size_t)row * D_X;
    float s = 0.f, tt = 0.f;
    for (int i = threadIdx.x; i < D_X; i += 128) {
        float v = xr[i];
        s  = fmaf(v, v, s);
        tt = fmaf(v, W_tau[i], tt);
    }
    #pragma unroll
    for (int o = 16; o > 0; o >>= 1) {
        s  += __shfl_xor_sync(~0u, s, o);
        tt += __shfl_xor_sync(~0u, tt, o);
    }
    __shared__ float sh[8];
    int w = threadIdx.x >> 5, l = threadIdx.x & 31;
    if (l == 0) { sh[w] = s; sh[4 + w] = tt; }
    __syncthreads();
    if (threadIdx.x == 0) {
        float S = sh[0] + sh[1] + sh[2] + sh[3];
        float T = sh[4] + sh[5] + sh[6] + sh[7] + b_tau[0];
        g_sq[row] = S;
        float tau = 1.f / (1.f + expf(-T));
        float kf  = rintf(16.f - 12.f * tau);
        kf = fminf(fmaxf(kf, 1.f), 16.f);
        g_k[row] = (int)kf;
    }
}

// ============================================================
// shared 128x128 GEMM mainloop: 4 warps (2x2), warp tile 64x64,
// virtual K = 1152 via 18 stages of 64 with offset maps.
// ============================================================
__device__ __forceinline__ void stage_load(uint32_t sbase,
                                           const __nv_bfloat16* gA,
                                           const __nv_bfloat16* gB, int tid) {
    #pragma unroll
    for (int it = 0; it < 8; it++) {
        int idx = tid + it * 128;          // 0..1023
        int r = idx >> 3, c = idx & 7;
        uint32_t off = (uint32_t)(r * 128 + c * 16);
        off ^= (off >> 3) & 0x70;
        CP_ASYNC16(sbase + off,         (const char*)(gA + (size_t)r * KPACK) + c * 16);
        CP_ASYNC16(sbase + 16384 + off, (const char*)(gB + (size_t)r * KPACK) + c * 16);
    }
}

__device__ __forceinline__ void gemm_tile(uint32_t stage_base,
    const __nv_bfloat16* gA0, const __nv_bfloat16* gB0, int tid,
    const uint32_t arow_off[4], const uint32_t arow_x[4],
    const uint32_t brow_off[4], const uint32_t brow_x[4],
    uint32_t a_hi, uint32_t b_hi, float acc[4][8][4]) {

    #pragma unroll
    for (int i = 0; i < 4; i++)
        #pragma unroll
        for (int j = 0; j < 8; j++)
            #pragma unroll
            for (int q = 0; q < 4; q++) acc[i][j][q] = 0.f;

    stage_load(stage_base,           gA0 + aOffE(0), gB0 + bOffE(0), tid); CP_COMMIT();
    stage_load(stage_base + STAGE_B, gA0 + aOffE(1), gB0 + bOffE(1), tid); CP_COMMIT();

    for (int s = 0; s < NKSTAGE; s++) {
        if (s + 2 < NKSTAGE) { CP_WAIT1(); } else { CP_WAIT0(); }
        __syncthreads();
        if (s + 2 < NKSTAGE) {
            stage_load(stage_base + ((s + 2) % 3) * STAGE_B,
                       gA0 + aOffE(s + 2), gB0 + bOffE(s + 2), tid);
            CP_COMMIT();
        }
        uint32_t stA = stage_base + (s % 3) * STAGE_B;
        uint32_t stB = stA + 16384;
        #pragma unroll
        for (int kk = 0; kk < 4; kk++) {
            uint32_t a[4][4], b[4][4];
            #pragma unroll
            for (int i = 0; i < 4; i++) {
                uint32_t ck = (uint32_t)(2 * kk) + a_hi;
                uint32_t ad = stA + arow_off[i] + ((ck ^ arow_x[i]) << 4);
                LDSM4(a[i][0], a[i][1], a[i][2], a[i][3], ad);
            }
            #pragma unroll
            for (int p = 0; p < 4; p++) {
                uint32_t ck = (uint32_t)(2 * kk) + b_hi;
                uint32_t ad = stB + brow_off[p] + ((ck ^ brow_x[p]) << 4);
                LDSM4(b[p][0], b[p][1], b[p][2], b[p][3], ad);
            }
            #pragma unroll
            for (int i = 0; i < 4; i++)
                #pragma unroll
                for (int j = 0; j < 8; j++)
                    MMA16816(acc[i][j], a[i], b[j >> 1][(j & 1) * 2], b[j >> 1][(j & 1) * 2 + 1]);
        }
    }
}

// ============================================================
// 3) knn: bf16 mma pairwise dot + fused top-16
//    grid (64, 4): 128 rows x 2048 cols per CTA; 128 threads, 4 warps (2x2)
// ============================================================
__global__ __launch_bounds__(128, 2) void knn_kernel() {
    extern __shared__ char smem[];
    uint32_t smem_base = smem_u32(smem);
    float* sqj = (float*)smem;
    int tid = threadIdx.x, lane = tid & 31, warp = tid >> 5;
    int wm = warp >> 1, wn = warp & 1;

    int rowBase  = blockIdx.x * MTILE;
    int colStart = blockIdx.y * JCHUNK;

    uint32_t a_hi = (uint32_t)((lane >> 4) & 1);
    uint32_t b_hi = (uint32_t)((lane >> 3) & 1);
    int aRow = wm * 64 + (lane & 15);
    int bRow = wn * 64 + (lane & 7) + (((lane >> 4) & 1) << 3);
    uint32_t arow_off[4], arow_x[4], brow_off[4], brow_x[4];
    #pragma unroll
    for (int i = 0; i < 4; i++) { int r = aRow + i * 16; arow_off[i] = r * 128; arow_x[i] = r & 7; }
    #pragma unroll
    for (int p = 0; p < 4; p++) { int r = bRow + p * 16; brow_off[p] = r * 128; brow_x[p] = r & 7; }

    float dist[16]; int idxr[16];
    #pragma unroll
    for (int p = 0; p < 16; p++) { dist[p] = CUDART_INF_F; idxr[p] = 0x7fffffff; }

    const __nv_bfloat16* gA0 = g_xp + (size_t)rowBase * KPACK;

    for (int t = 0; t < NT_PER; t++) {
        int colBase = colStart + t * NTILE;
        __syncthreads();                     // protect prev sD/sqj reads
        sqj[tid] = g_sq[colBase + tid];
        const __nv_bfloat16* gB0 = g_xp + (size_t)colBase * KPACK;

        float acc[4][8][4];
        gemm_tile(smem_base + 1024, gA0, gB0, tid,
                  arow_off, arow_x, brow_off, brow_x, a_hi, b_hi, acc);

        // ---- epilogue: acc -> smem d-tile -> owner top-16 scan ----
        __syncthreads();                     // all warps done reading stage bufs
        float* sD = (float*)(smem + 1024);
        int r0l = wm * 64 + (lane >> 2);
        int c0l = wn * 64 + (lane & 3) * 2;
        #pragma unroll
        for (int i = 0; i < 4; i++) {
            int r = r0l + i * 16;
            #pragma unroll
            for (int j = 0; j < 8; j++) {
                int c = c0l + j * 8;
                sD[r * 129 + c]           = acc[i][j][0];
                sD[r * 129 + c + 1]       = acc[i][j][1];
                sD[(r + 8) * 129 + c]     = acc[i][j][2];
                sD[(r + 8) * 129 + c + 1] = acc[i][j][3];
            }
        }
        __syncthreads();
        #pragma unroll 4
        for (int c = 0; c < 128; c++) {
            float d = fmaf(-2.f, sD[tid * 129 + c], sqj[c]);
            if (d < dist[15]) {
                float dd = d; int jj = colBase + c;
                #pragma unroll
                for (int p = 0; p < 16; p++) {
                    if (dd < dist[p]) {
                        float td = dist[p]; dist[p] = dd; dd = td;
                        int   tj = idxr[p]; idxr[p] = jj; jj = tj;
                    }
                }
            }
        }
    }

    int row = rowBase + tid;
    size_t base = ((size_t)blockIdx.y * B_N + row) * KMAX;
    #pragma unroll
    for (int p = 0; p < 16; p++) { g_cd[base + p] = dist[p]; g_ci[base + p] = idxr[p]; }
}

// ============================================================
// 2) proj via mma: h = relu(x @ W_proj + b_proj); grid (64, 2), 128 threads
// ============================================================
__global__ __launch_bounds__(128, 2) void projmma_kernel(const float* __restrict__ b_proj) {
    extern __shared__ char smem[];
    uint32_t smem_base = smem_u32(smem);
    int tid = threadIdx.x, lane = tid & 31, warp = tid >> 5;
    int wm = warp >> 1, wn = warp & 1;

    int rowBase = blockIdx.x * MTILE;
    int colTile = blockIdx.y * NTILE;

    uint32_t a_hi = (uint32_t)((lane >> 4) & 1);
    uint32_t b_hi = (uint32_t)((lane >> 3) & 1);
    int aRow = wm * 64 + (lane & 15);
    int bRow = wn * 64 + (lane & 7) + (((lane >> 4) & 1) << 3);
    uint32_t arow_off[4], arow_x[4], brow_off[4], brow_x[4];
    #pragma unroll
    for (int i = 0; i < 4; i++) { int r = aRow + i * 16; arow_off[i] = r * 128; arow_x[i] = r & 7; }
    #pragma unroll
    for (int p = 0; p < 4; p++) { int r = bRow + p * 16; brow_off[p] = r * 128; brow_x[p] = r & 7; }

    float acc[4][8][4];
    gemm_tile(smem_base + 1024,
              g_xp + (size_t)rowBase * KPACK,
              g_wp + (size_t)colTile * KPACK, tid,
              arow_off, arow_x, brow_off, brow_x, a_hi, b_hi, acc);

    int r0l = rowBase + wm * 64 + (lane >> 2);
    int c0l = colTile + wn * 64 + (lane & 3) * 2;
    #pragma unroll
    for (int j = 0; j < 8; j++) {
        int c = c0l + j * 8;
        float bp0 = b_proj[c], bp1 = b_proj[c + 1];
        #pragma unroll
        for (int i = 0; i < 4; i++) {
            int r = r0l + i * 16;
            g_h[(size_t)r * H_N + c]           = fmaxf(acc[i][j][0] + bp0, 0.f);
            g_h[(size_t)r * H_N + c + 1]       = fmaxf(acc[i][j][1] + bp1, 0.f);
            g_h[(size_t)(r + 8) * H_N + c]     = fmaxf(acc[i][j][2] + bp0, 0.f);
            g_h[(size_t)(r + 8) * H_N + c + 1] = fmaxf(acc[i][j][3] + bp1, 0.f);
        }
    }
}

// ============================================================
// 4) merge 4 partial top-16 lists (lexicographic (dist, idx))
// ============================================================
__global__ void merge_kernel() {
    int row = blockIdx.x * 64 + threadIdx.x;
    float dist[16]; int idxr[16];
    #pragma unroll
    for (int p = 0; p < 16; p++) { dist[p] = CUDART_INF_F; idxr[p] = 0x7fffffff; }
    for (int s = 0; s < JSPLIT; s++) {
        size_t base = ((size_t)s * B_N + row) * KMAX;
        for (int q = 0; q < 16; q++) {
            float d = g_cd[base + q]; int j = g_ci[base + q];
            bool enter = (d < dist[15]) || (d == dist[15] && j < idxr[15]);
            if (enter) {
                float dd = d; int jj = j;
                #pragma unroll
                for (int p = 0; p < 16; p++) {
                    bool lt = (dd < dist[p]) || (dd == dist[p] && jj < idxr[p]);
                    if (lt) {
                        float td = dist[p]; dist[p] = dd; dd = td;
                        int   tj = idxr[p]; idxr[p] = jj; jj = tj;
                    }
                }
            }
        }
    }
    #pragma unroll
    for (int p = 0; p < 16; p++) g_idx[(size_t)row * KMAX + p] = idxr[p];
}

// ============================================================
// 5) fused: agg gather + residual + LayerNorm + fc
// ============================================================
__global__ __launch_bounds__(256) void resln_kernel(const float* __restrict__ W_res,
                                                    const float* __restrict__ b_res,
                                                    const float* __restrict__ ln_g,
                                                    const float* __restrict__ ln_b,
                                                    const float* __restrict__ W_fc,
                                                    const float* __restrict__ b_fc,
                                                    float* __restrict__ out) {
    __shared__ float sAgg[16][256];
    __shared__ float sZ[16][256];
    __shared__ float sG[256], sBn[256], sWfc[256 * 6], sbfc[6];
    __shared__ int sidx[16][16];
    __shared__ int sK[16];
    __shared__ float sKi[16];
    int j = threadIdx.x;
    int r0 = blockIdx.x * 16;

    { int rr = j >> 4, q = j & 15; sidx[rr][q] = g_idx[(size_t)(r0 + rr) * KMAX + q]; }
    if (j < 16) { int k = g_k[r0 + j]; sK[j] = k; sKi[j] = 1.f / (float)k; }
    sG[j] = ln_g[j]; sBn[j] = ln_b[j];
    for (int l = j; l < 256 * 6; l += 256) sWfc[l] = W_fc[l];
    if (j < 6) sbfc[j] = b_fc[j];
    float br = b_res[j];
    __syncthreads();

    // agg gather
    for (int r = 0; r < 16; r++) {
        int k = sK[r];
        float s = 0.f;
        for (int t = 0; t < k; t++) s += g_h[(size_t)sidx[r][t] * H_N + j];
        sAgg[r][j] = s * sKi[r];
    }
    __syncthreads();

    float acc[16];
    #pragma unroll
    for (int r = 0; r < 16; r++) acc[r] = 0.f;
    for (int t = 0; t < 256; t++) {
        float w = W_res[(size_t)t * H_N + j];
        #pragma unroll
        for (int r = 0; r < 16; r++) acc[r] = fmaf(sAgg[r][t], w, acc[r]);
    }
    #pragma unroll
    for (int r = 0; r < 16; r++) {
        float rv = fmaxf(acc[r] + br, 0.f);
        sZ[r][j] = g_h[(size_t)(r0 + r) * H_N + j] + rv;
    }
    __syncthreads();

    int wid = j >> 5, lane = j & 31;
    for (int rr = 0; rr < 2; rr++) {
        int lr = wid * 2 + rr;
        int row = r0 + lr;
        float zv[8]; float s = 0.f, s2 = 0.f;
        #pragma unroll
        for (int q = 0; q < 8; q++) {
            zv[q] = sZ[lr][lane + q * 32];
            s += zv[q]; s2 = fmaf(zv[q], zv[q], s2);
        }
        #pragma unroll
        for (int o = 16; o > 0; o >>= 1) {
            s  += __shfl_xor_sync(~0u, s,  o);
            s2 += __shfl_xor_sync(~0u, s2, o);
        }
        float mu   = s * (1.f / 256.f);
        float var  = s2 * (1.f / 256.f) - mu * mu;
        float rstd = 1.0f / sqrtf(var + 1e-5f);
        float po[6] = {0, 0, 0, 0, 0, 0};
        #pragma unroll
        for (int q = 0; q < 8; q++) {
            int tcol = lane + q * 32;
            float a = (zv[q] - mu) * rstd * sG[tcol] + sBn[tcol];
            #pragma unroll
            for (int c = 0; c < 6; c++) po[c] = fmaf(a, sWfc[tcol * 6 + c], po[c]);
        }
        #pragma unroll
        for (int c = 0; c < 6; c++) {
            #pragma unroll
            for (int o = 16; o > 0; o >>= 1) po[c] += __shfl_xor_sync(~0u, po[c], o);
        }
        if (lane == 0) {
            #pragma unroll
            for (int c = 0; c < 6; c++) out[(size_t)row * C_N + c] = po[c] + sbfc[c];
        }
    }
}

// ============================================================
extern "C" void kernel_launch(void* const* d_in, const int* in_sizes, int n_in,
                              void* d_out, int out_size) {
    const float* x      = (const float*)d_in[0];
    const float* W_proj = (const float*)d_in[1];
    const float* b_proj = (const float*)d_in[2];
    const float* W_tau  = (const float*)d_in[3];
    const float* b_tau  = (const float*)d_in[4];
    const float* W_res  = (const float*)d_in[5];
    const float* b_res  = (const float*)d_in[6];
    const float* ln_g   = (const float*)d_in[7];
    const float* ln_b   = (const float*)d_in[8];
    const float* W_fc   = (const float*)d_in[9];
    const float* b_fc   = (const float*)d_in[10];
    float* out = (float*)d_out;

    cudaFuncSetAttribute(knn_kernel,     cudaFuncAttributeMaxDynamicSharedMemorySize, KNN_SMEM);
    cudaFuncSetAttribute(projmma_kernel, cudaFuncAttributeMaxDynamicSharedMemorySize, KNN_SMEM);

    prep_kernel<<<B_N, 128>>>(x, W_tau, b_tau);
    pack_kernel<<<(B_N * D_X / 4) / 256, 256>>>(x);
    packw_kernel<<<(D_X * H_N) / 256, 256>>>(W_proj);
    projmma_kernel<<<dim3(B_N / MTILE, H_N / NTILE), 128, KNN_SMEM>>>(b_proj);
    dim3 g(B_N / MTILE, JSPLIT);
    knn_kernel<<<g, 128, KNN_SMEM>>>();
    merge_kernel<<<B_N / 64, 64>>>();
    resln_kernel<<<B_N / 16, 256>>>(W_res, b_res, ln_g, ln_b, W_fc, b_fc, out);
}